// round 9
// baseline (speedup 1.0000x reference)
#include <cuda_runtime.h>
#include <math.h>

#define NB 15
#define NC 4096
#define BATCH 512
#define ZCH 37              // z-chunks per group; 37*4*15 = 2220 CTAs = 3 exact waves
#define NCC 4               // c-chunks of 1024 floats
#define NGROUP (NB * NCC)   // 60 reduction groups

// Scratch (allocation-free)
__device__ float        g_partial[NGROUP * ZCH * 1024];  // [group][z][1024]
__device__ float2       g_bpart[NGROUP];                 // per group: {sum m, sum m^2}
__device__ unsigned int g_gctr[NGROUP];                  // per-group arrival counters
__device__ unsigned int g_ctr;                           // global group counter

// ---------------------------------------------------------------------------
// Single fused kernel, z = blockIdx.x (fastest) so each group's 37 blocks are
// consecutive -> complete in the same wave -> group reduction overlaps the
// remaining DRAM streaming and reads L2-hot partials.
//  phase A: stream-reduce 13-14 batch rows x 1024 channels (__ldcs input).
//  phase B (last arriver of each group): reduce 37 L2-hot partials.
//  phase C (last group): per-base stats + final fp32 loss on warp 0.
// grid = (ZCH, NCC, NB), block = 256
// ---------------------------------------------------------------------------
__global__ void __launch_bounds__(256) k_fused(const float* __restrict__ in,
                                               float* __restrict__ out)
{
    const int z   = blockIdx.x;
    const int cc  = blockIdx.y;
    const int b   = blockIdx.z;
    const int tid = threadIdx.x;
    const int g   = b * NCC + cc;

    // ---- phase A: batch reduction for this (b, cc, z) slice ----
    const int r0 = (z * BATCH) / ZCH;
    const int r1 = ((z + 1) * BATCH) / ZCH;
    const int n  = r1 - r0;

    const int c = cc * 1024 + tid * 4;
    const size_t rs4 = (size_t)NB * NC / 4;
    const float4* p = (const float4*)(in + ((size_t)r0 * NB + b) * NC + c);

    float4 a0 = make_float4(0.f, 0.f, 0.f, 0.f);
    float4 a1 = a0, a2 = a0, a3 = a0;

    int i = 0;
    for (; i + 3 < n; i += 4) {
        float4 v0 = __ldcs(p + (size_t)(i + 0) * rs4);
        float4 v1 = __ldcs(p + (size_t)(i + 1) * rs4);
        float4 v2 = __ldcs(p + (size_t)(i + 2) * rs4);
        float4 v3 = __ldcs(p + (size_t)(i + 3) * rs4);
        a0.x += v0.x; a0.y += v0.y; a0.z += v0.z; a0.w += v0.w;
        a1.x += v1.x; a1.y += v1.y; a1.z += v1.z; a1.w += v1.w;
        a2.x += v2.x; a2.y += v2.y; a2.z += v2.z; a2.w += v2.w;
        a3.x += v3.x; a3.y += v3.y; a3.z += v3.z; a3.w += v3.w;
    }
    for (; i < n; i++) {
        float4 v = __ldcs(p + (size_t)i * rs4);
        a0.x += v.x; a0.y += v.y; a0.z += v.z; a0.w += v.w;
    }

    float4 acc;
    acc.x = (a0.x + a1.x) + (a2.x + a3.x);
    acc.y = (a0.y + a1.y) + (a2.y + a3.y);
    acc.z = (a0.z + a1.z) + (a2.z + a3.z);
    acc.w = (a0.w + a1.w) + (a2.w + a3.w);

    *(float4*)&g_partial[((size_t)g * ZCH + z) * 1024 + tid * 4] = acc;

    // ---- group arrival: last arriver of the 37 z-blocks reduces the group ----
    __threadfence();
    __syncthreads();
    __shared__ int sh_grdy;
    if (tid == 0) {
        unsigned int old = atomicAdd(&g_gctr[g], 1u);
        sh_grdy = (old == ZCH - 1) ? 1 : 0;
        if (sh_grdy) g_gctr[g] = 0;   // reset for next replay (sole reader)
    }
    __syncthreads();
    if (!sh_grdy) return;

    // ---- phase B: reduce 37 partials (L2-hot) for 1024 channels ----
    __threadfence();   // acquire other blocks' partial writes

    const float4* q = (const float4*)&g_partial[(size_t)g * ZCH * 1024 + tid * 4];

    float4 t0 = make_float4(0.f, 0.f, 0.f, 0.f);
    float4 t1 = t0, t2 = t0, t3 = t0;
    #pragma unroll
    for (int zz = 0; zz + 3 < ZCH; zz += 4) {
        float4 v0 = q[(zz + 0) * 256];
        float4 v1 = q[(zz + 1) * 256];
        float4 v2 = q[(zz + 2) * 256];
        float4 v3 = q[(zz + 3) * 256];
        t0.x += v0.x; t0.y += v0.y; t0.z += v0.z; t0.w += v0.w;
        t1.x += v1.x; t1.y += v1.y; t1.z += v1.z; t1.w += v1.w;
        t2.x += v2.x; t2.y += v2.y; t2.z += v2.z; t2.w += v2.w;
        t3.x += v3.x; t3.y += v3.y; t3.z += v3.z; t3.w += v3.w;
    }
    {   // z = 36 remainder
        float4 v = q[36 * 256];
        t0.x += v.x; t0.y += v.y; t0.z += v.z; t0.w += v.w;
    }
    float4 t;
    t.x = (t0.x + t1.x) + (t2.x + t3.x);
    t.y = (t0.y + t1.y) + (t2.y + t3.y);
    t.z = (t0.z + t1.z) + (t2.z + t3.z);
    t.w = (t0.w + t1.w) + (t2.w + t3.w);

    const float inv_batch = 1.0f / (float)BATCH;   // exact
    float m0 = t.x * inv_batch;
    float m1 = t.y * inv_batch;
    float m2 = t.z * inv_batch;
    float m3 = t.w * inv_batch;

    float s  = (m0 + m1) + (m2 + m3);
    float s2 = fmaf(m0, m0, m1 * m1) + fmaf(m2, m2, m3 * m3);

    #pragma unroll
    for (int off = 16; off > 0; off >>= 1) {
        s  += __shfl_xor_sync(0xffffffffu, s,  off);
        s2 += __shfl_xor_sync(0xffffffffu, s2, off);
    }

    __shared__ float rs[8], rs2[8];
    if ((tid & 31) == 0) { rs[tid >> 5] = s; rs2[tid >> 5] = s2; }
    __syncthreads();

    __shared__ int sh_last;
    if (tid == 0) {
        float sum   = ((rs[0] + rs[1]) + (rs[2] + rs[3]))
                    + ((rs[4] + rs[5]) + (rs[6] + rs[7]));
        float sumsq = ((rs2[0] + rs2[1]) + (rs2[2] + rs2[3]))
                    + ((rs2[4] + rs2[5]) + (rs2[6] + rs2[7]));
        g_bpart[g] = make_float2(sum, sumsq);
        __threadfence();
        unsigned int old = atomicAdd(&g_ctr, 1u);
        sh_last = (old == NGROUP - 1) ? 1 : 0;
    }
    __syncthreads();
    if (!sh_last || tid >= 32) return;

    // ---- phase C: last group, warp 0: per-base stats + final loss ----
    __threadfence();   // acquire all groups' g_bpart

    const int l = tid;
    __shared__ float sh_mean[NB], sh_std[NB];

    if (l < NB) {
        float2 p0 = g_bpart[l * NCC + 0];
        float2 p1 = g_bpart[l * NCC + 1];
        float2 p2 = g_bpart[l * NCC + 2];
        float2 p3 = g_bpart[l * NCC + 3];
        float sum   = (p0.x + p1.x) + (p2.x + p3.x);
        float sumsq = (p0.y + p1.y) + (p2.y + p3.y);
        float mean = sum * (1.0f / (float)NC);            // exact scale
        float var  = (sumsq - sum * sum * (1.0f / (float)NC)) * (1.0f / (float)(NC - 1));
        if (var < 0.f) var = 0.f;
        sh_mean[l] = mean;
        sh_std[l]  = sqrtf(var);
    }
    __syncwarp();

    // groups: [0,3) [3,5) [5,6) [6,10) [10,12) [12,15)
    const int starts[7] = {0, 3, 5, 6, 10, 12, 15};
    const int G = 6;
    const int pi[15] = {0,0,0,0,0, 1,1,1,1, 2,2,2, 3,3, 4};
    const int pj[15] = {1,2,3,4,5, 2,3,4,5, 3,4,5, 4,5, 5};

    __shared__ float sh_ss[6], sh_mn[6], sh_msum[6], sh_pair[15], sh_lt[6];

    if (l < G) {
        const int s0 = starts[l], s1 = starts[l + 1];
        const int ng = s1 - s0;
        if (ng == 1) {
            sh_ss[l]   = sh_std[s0];
            sh_msum[l] = sh_mean[s0];
            sh_mn[l]   = sh_mean[s0];
        } else {
            float ms = 0.f, mm = 0.f;
            for (int k = s0; k < s1; k++) { ms += sh_std[k]; mm += sh_mean[k]; }
            ms /= (float)ng; mm /= (float)ng;
            float vs = 0.f, vm = 0.f;
            for (int k = s0; k < s1; k++) {
                float d = sh_std[k]  - ms; vs = fmaf(d, d, vs);
                float e = sh_mean[k] - mm; vm = fmaf(e, e, vm);
            }
            sh_ss[l]   = sqrtf(vs / (float)(ng - 1));
            sh_msum[l] = sqrtf(vm / (float)(ng - 1));
            sh_mn[l]   = mm;
        }
    }
    __syncwarp();

    if (l < 15) {
        float d1 = sh_ss[pi[l]] - sh_ss[pj[l]];
        float d2 = sh_mn[pi[l]] - sh_mn[pj[l]];
        sh_pair[l] = expf(d1 * d1) + expf(d2 * d2);   // MEAN_STD = 1.0
    }
    __syncwarp();

    if (l < G) {
        float subloss = 5e-5f;
        #pragma unroll
        for (int p2i = 0; p2i < 15; p2i++)
            if (pi[p2i] == l) subloss += sh_pair[p2i];
        sh_lt[l] = logf(1.0f + sh_msum[l] / (subloss + sh_msum[l]));
    }
    __syncwarp();

    if (l == 0) {
        float loss = 0.f;
        #pragma unroll
        for (int gg = 0; gg < G; gg++) loss += sh_lt[gg];
        out[0] = loss;
        g_ctr = 0;   // reset for next graph replay
    }
}

// ---------------------------------------------------------------------------
extern "C" void kernel_launch(void* const* d_in, const int* in_sizes, int n_in,
                              void* d_out, int out_size)
{
    const float* meta1 = (const float*)d_in[0];

    dim3 g1(ZCH, NCC, NB);   // z fastest: group's 37 blocks are consecutive
    k_fused<<<g1, 256>>>(meta1, (float*)d_out);
}

// round 10
// speedup vs baseline: 1.1935x; 1.1935x over previous
#include <cuda_runtime.h>
#include <math.h>

#define NB 15
#define NC 4096
#define BATCH 512
#define ZCH 10            // z-chunks: 4*15*10 = 600 CTAs = ONE resident wave
#define NCC 4             // c-chunks of 1024 floats

// Scratch (allocation-free): only 2.46 MB of partials -> stays L2-hot
__device__ float        g_partial[NB * ZCH * NC];   // [b][z][c]
__device__ float2       g_bpart[NB * NCC];          // per (b, cchunk): {sum m, sum m^2}
__device__ unsigned int g_ctr;                      // zero-init; reset by last block

// ---------------------------------------------------------------------------
// Kernel 1: batch-dimension reduction (HBM-bound, reads all 125.8 MB).
// Single resident wave: all partial writes happen in the last ~µs of the
// kernel, so they remain in L2 for kernel 2. __ldcs keeps the input stream
// evict-first.
// grid = (NCC, NB, ZCH), block = 256, each thread owns one float4 of C
// ---------------------------------------------------------------------------
__global__ void __launch_bounds__(256) k1_batch_reduce(const float* __restrict__ in)
{
    const int cc = blockIdx.x;
    const int b  = blockIdx.y;
    const int z  = blockIdx.z;
    const int c  = cc * 1024 + threadIdx.x * 4;

    // uneven split of 512 rows into 10 chunks (sizes 51/52)
    const int r0 = (z * BATCH) / ZCH;
    const int r1 = ((z + 1) * BATCH) / ZCH;
    const int n  = r1 - r0;

    const size_t rs4 = (size_t)NB * NC / 4;
    const float4* p = (const float4*)(in + ((size_t)r0 * NB + b) * NC + c);

    float4 a0 = make_float4(0.f, 0.f, 0.f, 0.f);
    float4 a1 = a0, a2 = a0, a3 = a0;

    int i = 0;
    for (; i + 3 < n; i += 4) {
        float4 v0 = __ldcs(p + (size_t)(i + 0) * rs4);
        float4 v1 = __ldcs(p + (size_t)(i + 1) * rs4);
        float4 v2 = __ldcs(p + (size_t)(i + 2) * rs4);
        float4 v3 = __ldcs(p + (size_t)(i + 3) * rs4);
        a0.x += v0.x; a0.y += v0.y; a0.z += v0.z; a0.w += v0.w;
        a1.x += v1.x; a1.y += v1.y; a1.z += v1.z; a1.w += v1.w;
        a2.x += v2.x; a2.y += v2.y; a2.z += v2.z; a2.w += v2.w;
        a3.x += v3.x; a3.y += v3.y; a3.z += v3.z; a3.w += v3.w;
    }
    for (; i < n; i++) {
        float4 v = __ldcs(p + (size_t)i * rs4);
        a0.x += v.x; a0.y += v.y; a0.z += v.z; a0.w += v.w;
    }

    float4 acc;
    acc.x = (a0.x + a1.x) + (a2.x + a3.x);
    acc.y = (a0.y + a1.y) + (a2.y + a3.y);
    acc.z = (a0.z + a1.z) + (a2.z + a3.z);
    acc.w = (a0.w + a1.w) + (a2.w + a3.w);

    *(float4*)&g_partial[((b * ZCH + z) * NC) + c] = acc;
}

// ---------------------------------------------------------------------------
// Kernel 2 (fused, fp32): grid (NCC, NB) = 60 blocks of 256 threads.
// Each thread owns one float4 column and sums its 10 z-partials (all
// independent loads, L2-hot). Block reduces (sum m, sum m^2); the last block
// computes per-base stats + the final loss.
// ---------------------------------------------------------------------------
__global__ void __launch_bounds__(256) k2_stats_and_loss(float* __restrict__ out)
{
    const int b   = blockIdx.y;
    const int cc  = blockIdx.x;
    const int tid = threadIdx.x;

    const int c = cc * 1024 + tid * 4;   // float index
    const float4* base = (const float4*)&g_partial[(size_t)(b * ZCH) * NC + c];
    const size_t rs4 = NC / 4;

    // 10 independent loads, fixed-order tree sum
    float4 v0 = base[0 * rs4];
    float4 v1 = base[1 * rs4];
    float4 v2 = base[2 * rs4];
    float4 v3 = base[3 * rs4];
    float4 v4 = base[4 * rs4];
    float4 v5 = base[5 * rs4];
    float4 v6 = base[6 * rs4];
    float4 v7 = base[7 * rs4];
    float4 v8 = base[8 * rs4];
    float4 v9 = base[9 * rs4];

    float4 t;
    t.x = (((v0.x + v1.x) + (v2.x + v3.x)) + ((v4.x + v5.x) + (v6.x + v7.x))) + (v8.x + v9.x);
    t.y = (((v0.y + v1.y) + (v2.y + v3.y)) + ((v4.y + v5.y) + (v6.y + v7.y))) + (v8.y + v9.y);
    t.z = (((v0.z + v1.z) + (v2.z + v3.z)) + ((v4.z + v5.z) + (v6.z + v7.z))) + (v8.z + v9.z);
    t.w = (((v0.w + v1.w) + (v2.w + v3.w)) + ((v4.w + v5.w) + (v6.w + v7.w))) + (v8.w + v9.w);

    const float inv_batch = 1.0f / (float)BATCH;   // exact
    float m0 = t.x * inv_batch;
    float m1 = t.y * inv_batch;
    float m2 = t.z * inv_batch;
    float m3 = t.w * inv_batch;

    float s  = (m0 + m1) + (m2 + m3);
    float s2 = fmaf(m0, m0, m1 * m1) + fmaf(m2, m2, m3 * m3);

    #pragma unroll
    for (int off = 16; off > 0; off >>= 1) {
        s  += __shfl_xor_sync(0xffffffffu, s,  off);
        s2 += __shfl_xor_sync(0xffffffffu, s2, off);
    }

    __shared__ float rs[8], rs2[8];
    if ((tid & 31) == 0) { rs[tid >> 5] = s; rs2[tid >> 5] = s2; }
    __syncthreads();

    __shared__ int sh_last;
    if (tid == 0) {
        float sum   = ((rs[0] + rs[1]) + (rs[2] + rs[3]))
                    + ((rs[4] + rs[5]) + (rs[6] + rs[7]));
        float sumsq = ((rs2[0] + rs2[1]) + (rs2[2] + rs2[3]))
                    + ((rs2[4] + rs2[5]) + (rs2[6] + rs2[7]));
        g_bpart[b * NCC + cc] = make_float2(sum, sumsq);
        __threadfence();
        unsigned int old = atomicAdd(&g_ctr, 1u);
        sh_last = (old == NB * NCC - 1) ? 1 : 0;
    }
    __syncthreads();
    if (!sh_last || tid >= 32) return;

    // ---- last block, warp 0: per-base stats + final loss (all fp32) ----
    __threadfence();   // acquire all blocks' g_bpart

    const int l = tid;
    __shared__ float sh_mean[NB], sh_std[NB];

    if (l < NB) {
        float2 p0 = g_bpart[l * NCC + 0];
        float2 p1 = g_bpart[l * NCC + 1];
        float2 p2 = g_bpart[l * NCC + 2];
        float2 p3 = g_bpart[l * NCC + 3];
        float sum   = (p0.x + p1.x) + (p2.x + p3.x);
        float sumsq = (p0.y + p1.y) + (p2.y + p3.y);
        float mean = sum * (1.0f / (float)NC);            // exact scale
        float var  = (sumsq - sum * sum * (1.0f / (float)NC)) * (1.0f / (float)(NC - 1));
        if (var < 0.f) var = 0.f;
        sh_mean[l] = mean;
        sh_std[l]  = sqrtf(var);
    }
    __syncwarp();

    // groups: [0,3) [3,5) [5,6) [6,10) [10,12) [12,15)
    const int starts[7] = {0, 3, 5, 6, 10, 12, 15};
    const int G = 6;
    const int pi[15] = {0,0,0,0,0, 1,1,1,1, 2,2,2, 3,3, 4};
    const int pj[15] = {1,2,3,4,5, 2,3,4,5, 3,4,5, 4,5, 5};

    __shared__ float sh_ss[6], sh_mn[6], sh_msum[6], sh_pair[15], sh_lt[6];

    if (l < G) {
        const int s0 = starts[l], s1 = starts[l + 1];
        const int ng = s1 - s0;
        if (ng == 1) {
            sh_ss[l]   = sh_std[s0];
            sh_msum[l] = sh_mean[s0];
            sh_mn[l]   = sh_mean[s0];
        } else {
            float ms = 0.f, mm = 0.f;
            for (int k = s0; k < s1; k++) { ms += sh_std[k]; mm += sh_mean[k]; }
            ms /= (float)ng; mm /= (float)ng;
            float vs = 0.f, vm = 0.f;
            for (int k = s0; k < s1; k++) {
                float d = sh_std[k]  - ms; vs = fmaf(d, d, vs);
                float e = sh_mean[k] - mm; vm = fmaf(e, e, vm);
            }
            sh_ss[l]   = sqrtf(vs / (float)(ng - 1));
            sh_msum[l] = sqrtf(vm / (float)(ng - 1));
            sh_mn[l]   = mm;
        }
    }
    __syncwarp();

    if (l < 15) {
        float d1 = sh_ss[pi[l]] - sh_ss[pj[l]];
        float d2 = sh_mn[pi[l]] - sh_mn[pj[l]];
        sh_pair[l] = expf(d1 * d1) + expf(d2 * d2);   // MEAN_STD = 1.0
    }
    __syncwarp();

    if (l < G) {
        float subloss = 5e-5f;
        #pragma unroll
        for (int p = 0; p < 15; p++)
            if (pi[p] == l) subloss += sh_pair[p];
        sh_lt[l] = logf(1.0f + sh_msum[l] / (subloss + sh_msum[l]));
    }
    __syncwarp();

    if (l == 0) {
        float loss = 0.f;
        #pragma unroll
        for (int g = 0; g < G; g++) loss += sh_lt[g];
        out[0] = loss;
        g_ctr = 0;   // reset for next graph replay
    }
}

// ---------------------------------------------------------------------------
extern "C" void kernel_launch(void* const* d_in, const int* in_sizes, int n_in,
                              void* d_out, int out_size)
{
    const float* meta1 = (const float*)d_in[0];

    dim3 g1(NCC, NB, ZCH);   // (4, 15, 10) = 600 CTAs = single resident wave
    k1_batch_reduce<<<g1, 256>>>(meta1);

    dim3 g2(NCC, NB);        // 60 blocks x 256 threads
    k2_stats_and_loss<<<g2, 256>>>((float*)d_out);
}

// round 12
// speedup vs baseline: 1.2052x; 1.0098x over previous
#include <cuda_runtime.h>
#include <math.h>

#define NB 15
#define NC 4096
#define BATCH 512
#define CCH 128                 // c-chunks of 32 floats; grid = (128, 15) = 1920 blocks
#define NGROUP (NB * CCH)       // 1920

// Scratch (allocation-free): just 15 KB of per-block results
__device__ float2       g_bpart[NGROUP];   // [b][cc] -> {sum m, sum m^2} over 32 channels
__device__ unsigned int g_ctr;             // zero-init; reset by last block

// ---------------------------------------------------------------------------
// Single kernel. Each block fully reduces 512 batch rows x 32 channels of one
// base: one 128-byte line per row, perfectly coalesced. Thread layout:
// 8 float4-lanes x 32 z-slices of 16 rows. smem tree combines slices; warp 0
// (FULL warp — width-8 segmented shuffles) forms (sum m, sum m^2); thread 0
// stores one float2 + arrives. The LAST arriver reduces the 1920 L2-hot
// float2s and computes the loss.
// grid = (CCH, NB), block = 256
// ---------------------------------------------------------------------------
__global__ void __launch_bounds__(256) k_loss(const float* __restrict__ in,
                                              float* __restrict__ out)
{
    const int cc    = blockIdx.x;
    const int b     = blockIdx.y;
    const int tid   = threadIdx.x;
    const int lane4 = tid & 7;         // float4 lane within the 32-float chunk
    const int zsl   = tid >> 3;        // 32 z-slices of 16 rows
    const int g     = b * CCH + cc;

    // ---- phase A: reduce 16 rows for this (lane4, zsl) ----
    const size_t rs4 = (size_t)NB * NC / 4;   // float4 stride between batch rows
    const float4* p = (const float4*)(in + ((size_t)(zsl * 16) * NB + b) * NC
                                         + cc * 32 + lane4 * 4);

    float4 a0 = make_float4(0.f, 0.f, 0.f, 0.f);
    float4 a1 = a0, a2 = a0, a3 = a0;

    #pragma unroll
    for (int i = 0; i < 16; i += 4) {
        float4 v0 = __ldcs(p + (size_t)(i + 0) * rs4);
        float4 v1 = __ldcs(p + (size_t)(i + 1) * rs4);
        float4 v2 = __ldcs(p + (size_t)(i + 2) * rs4);
        float4 v3 = __ldcs(p + (size_t)(i + 3) * rs4);
        a0.x += v0.x; a0.y += v0.y; a0.z += v0.z; a0.w += v0.w;
        a1.x += v1.x; a1.y += v1.y; a1.z += v1.z; a1.w += v1.w;
        a2.x += v2.x; a2.y += v2.y; a2.z += v2.z; a2.w += v2.w;
        a3.x += v3.x; a3.y += v3.y; a3.z += v3.z; a3.w += v3.w;
    }

    float4 acc;
    acc.x = (a0.x + a1.x) + (a2.x + a3.x);
    acc.y = (a0.y + a1.y) + (a2.y + a3.y);
    acc.z = (a0.z + a1.z) + (a2.z + a3.z);
    acc.w = (a0.w + a1.w) + (a2.w + a3.w);

    // ---- combine the 32 z-slices via smem tree (same-lane combines) ----
    __shared__ float4 sh[256];
    sh[tid] = acc;
    __syncthreads();
    #pragma unroll
    for (int off = 128; off >= 8; off >>= 1) {
        if (tid < off) {
            float4 u = sh[tid + off];
            float4 t = sh[tid];
            t.x += u.x; t.y += u.y; t.z += u.z; t.w += u.w;
            sh[tid] = t;
        }
        __syncthreads();
    }

    // warp 0 (ALL 32 lanes) finishes: lanes 0-7 hold real data, 8-31 zeros.
    float s = 0.f, s2 = 0.f;
    if (tid < 32) {
        if (tid < 8) {
            float4 t = sh[tid];
            const float inv_batch = 1.0f / (float)BATCH;   // exact
            float m0 = t.x * inv_batch;
            float m1 = t.y * inv_batch;
            float m2 = t.z * inv_batch;
            float m3 = t.w * inv_batch;
            s  = (m0 + m1) + (m2 + m3);
            s2 = fmaf(m0, m0, m1 * m1) + fmaf(m2, m2, m3 * m3);
        }
        // width-8 segmented shuffles, executed by the FULL warp (no divergence)
        #pragma unroll
        for (int off = 4; off > 0; off >>= 1) {
            s  += __shfl_down_sync(0xffffffffu, s,  off, 8);
            s2 += __shfl_down_sync(0xffffffffu, s2, off, 8);
        }
    }

    __shared__ int sh_last;
    if (tid == 0) {
        g_bpart[g] = make_float2(s, s2);   // 8-byte store
        __threadfence();                   // cheap: only 8 B to drain
        unsigned int old = atomicAdd(&g_ctr, 1u);
        sh_last = (old == NGROUP - 1) ? 1 : 0;
    }
    __syncthreads();
    if (!sh_last) return;

    // =========== last arriver: reduce 1920 float2s + final loss ===========
    __threadfence();   // acquire all blocks' g_bpart

    __shared__ float sh_mean[NB], sh_std[NB];

    // base = tid>>4 (0..15), part = tid&15; 8 sequential float2 loads each.
    // ALL 256 threads execute the shuffles (width-16 segments, no divergence).
    {
        const int base = tid >> 4;
        const int part = tid & 15;
        float s = 0.f, s2 = 0.f;
        if (base < NB) {
            const float2* q = &g_bpart[base * CCH + part * 8];
            #pragma unroll
            for (int k = 0; k < 8; k++) { float2 v = q[k]; s += v.x; s2 += v.y; }
        }
        #pragma unroll
        for (int off = 8; off > 0; off >>= 1) {
            s  += __shfl_down_sync(0xffffffffu, s,  off, 16);
            s2 += __shfl_down_sync(0xffffffffu, s2, off, 16);
        }
        if (base < NB && part == 0) {
            float mean = s * (1.0f / (float)NC);           // exact scale
            float var  = (s2 - s * s * (1.0f / (float)NC)) * (1.0f / (float)(NC - 1));
            if (var < 0.f) var = 0.f;
            sh_mean[base] = mean;
            sh_std[base]  = sqrtf(var);
        }
    }
    __syncthreads();
    if (tid >= 32) return;

    // ---- warp 0: group stats + pairwise-exp loss (fp32, no shuffles) ----
    const int l = tid;
    // groups: [0,3) [3,5) [5,6) [6,10) [10,12) [12,15)
    const int starts[7] = {0, 3, 5, 6, 10, 12, 15};
    const int G = 6;
    const int pi[15] = {0,0,0,0,0, 1,1,1,1, 2,2,2, 3,3, 4};
    const int pj[15] = {1,2,3,4,5, 2,3,4,5, 3,4,5, 4,5, 5};

    __shared__ float sh_ss[6], sh_mn[6], sh_msum[6], sh_pair[15], sh_lt[6];

    if (l < G) {
        const int s0 = starts[l], s1 = starts[l + 1];
        const int ng = s1 - s0;
        if (ng == 1) {
            sh_ss[l]   = sh_std[s0];
            sh_msum[l] = sh_mean[s0];
            sh_mn[l]   = sh_mean[s0];
        } else {
            float ms = 0.f, mm = 0.f;
            for (int k = s0; k < s1; k++) { ms += sh_std[k]; mm += sh_mean[k]; }
            ms /= (float)ng; mm /= (float)ng;
            float vs = 0.f, vm = 0.f;
            for (int k = s0; k < s1; k++) {
                float d = sh_std[k]  - ms; vs = fmaf(d, d, vs);
                float e = sh_mean[k] - mm; vm = fmaf(e, e, vm);
            }
            sh_ss[l]   = sqrtf(vs / (float)(ng - 1));
            sh_msum[l] = sqrtf(vm / (float)(ng - 1));
            sh_mn[l]   = mm;
        }
    }
    __syncwarp();

    if (l < 15) {
        float d1 = sh_ss[pi[l]] - sh_ss[pj[l]];
        float d2 = sh_mn[pi[l]] - sh_mn[pj[l]];
        sh_pair[l] = expf(d1 * d1) + expf(d2 * d2);   // MEAN_STD = 1.0
    }
    __syncwarp();

    if (l < G) {
        float subloss = 5e-5f;
        #pragma unroll
        for (int p = 0; p < 15; p++)
            if (pi[p] == l) subloss += sh_pair[p];
        sh_lt[l] = logf(1.0f + sh_msum[l] / (subloss + sh_msum[l]));
    }
    __syncwarp();

    if (l == 0) {
        float loss = 0.f;
        #pragma unroll
        for (int g2 = 0; g2 < G; g2++) loss += sh_lt[g2];
        out[0] = loss;
        g_ctr = 0;   // reset for next graph replay
    }
}

// ---------------------------------------------------------------------------
extern "C" void kernel_launch(void* const* d_in, const int* in_sizes, int n_in,
                              void* d_out, int out_size)
{
    const float* meta1 = (const float*)d_in[0];

    dim3 g(CCH, NB);   // (128, 15) = 1920 blocks, 256 threads each
    k_loss<<<g, 256>>>(meta1, (float*)d_out);
}